// round 5
// baseline (speedup 1.0000x reference)
#include <cuda_runtime.h>

namespace {
constexpr int kB = 2, kNP = 4, kN = 64, kP = 24, kCin = 16, kC = 32, kT = 96;
constexpr int kRows = kB * kNP * kN * kP;                                // 12288
constexpr long long kAttElems = (long long)kB * kN * kN * kT * kC;       // 25165824
constexpr int kPad = 36;          // smem row stride (floats), 16B-aligned
constexpr float kLog2e = 1.4426950408889634f;
}

__device__ float g_h[kRows * kC];   // h = x @ W, (B*6144, 32) row-major

using u64 = unsigned long long;

__device__ __forceinline__ float ex2f(float x) {
    float r; asm("ex2.approx.f32 %0, %1;" : "=f"(r) : "f"(x)); return r;
}
__device__ __forceinline__ float rcpf(float x) {
    float r; asm("rcp.approx.f32 %0, %1;" : "=f"(r) : "f"(x)); return r;
}
__device__ __forceinline__ u64 pack2(float a, float b) {
    u64 r; asm("mov.b64 %0, {%1, %2};" : "=l"(r) : "f"(a), "f"(b)); return r;
}
__device__ __forceinline__ float2 unpack2(u64 v) {
    float2 f; asm("mov.b64 {%0, %1}, %2;" : "=f"(f.x), "=f"(f.y) : "l"(v)); return f;
}
__device__ __forceinline__ u64 mul2(u64 a, u64 b) {
    u64 r; asm("mul.rn.f32x2 %0, %1, %2;" : "=l"(r) : "l"(a), "l"(b)); return r;
}
__device__ __forceinline__ u64 add2(u64 a, u64 b) {
    u64 r; asm("add.rn.f32x2 %0, %1, %2;" : "=l"(r) : "l"(a), "l"(b)); return r;
}

// Kernel 1: h = x @ W. One thread = one row x 4-channel quad.
__global__ void h_kernel(const float* __restrict__ x, const float* __restrict__ W) {
    int gid = blockIdx.x * 256 + threadIdx.x;   // 98304 threads
    int q = gid & 7;                            // channel quad (c = 4q..4q+3)
    int row = gid >> 3;
    const float4* xr = (const float4*)(x + row * kCin);
    const float4* Wq = (const float4*)W + q;    // quad of W row k is at k*8+q
    float4 a0 = __ldg(xr), a1 = __ldg(xr + 1), a2 = __ldg(xr + 2), a3 = __ldg(xr + 3);
    float4 acc = make_float4(0.f, 0.f, 0.f, 0.f);
#define FMA4(s, k) { float4 w = __ldg(Wq + (k) * 8); \
    acc.x = fmaf(s, w.x, acc.x); acc.y = fmaf(s, w.y, acc.y); \
    acc.z = fmaf(s, w.z, acc.z); acc.w = fmaf(s, w.w, acc.w); }
    FMA4(a0.x, 0)  FMA4(a0.y, 1)  FMA4(a0.z, 2)  FMA4(a0.w, 3)
    FMA4(a1.x, 4)  FMA4(a1.y, 5)  FMA4(a1.z, 6)  FMA4(a1.w, 7)
    FMA4(a2.x, 8)  FMA4(a2.y, 9)  FMA4(a2.z, 10) FMA4(a2.w, 11)
    FMA4(a3.x, 12) FMA4(a3.y, 13) FMA4(a3.z, 14) FMA4(a3.w, 15)
#undef FMA4
    *(float4*)(g_h + row * kC + q * 4) = acc;
}

// Kernel 2: warp = (b,s,i,p); 4-lane group owns one j (8 j's per iter, 8 iters);
// lane owns 8 channels. f32x2 packed math; softmax denom via 2-stage shfl.
__global__ void __launch_bounds__(256, 4)
att_kernel(const float* __restrict__ adj, float* __restrict__ out) {
    __shared__ float hs[kN * kPad];    // 64 rows of h[b,s,j,p,:]
    __shared__ float as1[8 * kN];      // adj * log2e per (i,j)

    const int tid  = threadIdx.x;
    const int warp = tid >> 5;
    const int lane = tid & 31;
    const int cg   = lane & 3;         // channel oct: c = 8*cg .. 8*cg+7
    const int grp  = lane >> 2;        // j subgroup (0..7)

    const int p  = blockIdx.x % kP;
    const int bs = blockIdx.x / kP;
    const int s  = bs & 3;
    const int b  = bs >> 2;
    const int i0 = (int)blockIdx.y * 8;
    const int i  = i0 + warp;

    // Stage h rows (512 float4); row j lives at +j*768 floats in g_h
    const float4* hb = (const float4*)(g_h + (b * 6144 + s * 1536 + p) * 32);
#pragma unroll
    for (int r = 0; r < 2; ++r) {
        int idx = tid + r * 256;            // 0..511
        int jj = idx >> 3, q = idx & 7;
        *(float4*)(hs + jj * kPad + q * 4) = __ldg(hb + jj * 192 + q);
    }
#pragma unroll
    for (int r = 0; r < 2; ++r) {
        int idx = tid + r * 256;
        as1[idx] = __ldg(adj + (i0 + (idx >> 6)) * kN + (idx & 63)) * kLog2e;
    }
    __syncthreads();

    // h_i channels owned by this lane, packed into 4 f32x2 regs
    const float4 hu = *(const float4*)(hs + i * kPad + cg * 8);
    const float4 hv4 = *(const float4*)(hs + i * kPad + cg * 8 + 4);
    const u64 hi01 = pack2(hu.x, hu.y),  hi23 = pack2(hu.z, hu.w);
    const u64 hi45 = pack2(hv4.x, hv4.y), hi67 = pack2(hv4.z, hv4.w);
    const u64 C02 = pack2(0.2f, 0.2f);

    const int t = p * kNP + s;
    float* ob = out + (((long long)(b * kN + i) * kN) * kT + t) * kC + cg * 8;
    const float* aw = as1 + warp * kN;

    u64 rs01 = 0, rs23 = 0, rs45 = 0, rs67 = 0;   // 0x0 == (+0.f, +0.f)
#pragma unroll
    for (int jg = 0; jg < 8; ++jg) {
        const int j = jg * 8 + grp;
        const float4 u = *(const float4*)(hs + j * kPad + cg * 8);
        const float4 v = *(const float4*)(hs + j * kPad + cg * 8 + 4);
        const float a1 = aw[j];
        const u64 A = pack2(a1, a1);

        u64 x01 = mul2(pack2(u.x, u.y), hi01);
        u64 x23 = mul2(pack2(u.z, u.w), hi23);
        u64 x45 = mul2(pack2(v.x, v.y), hi45);
        u64 x67 = mul2(pack2(v.z, v.w), hi67);
        u64 t01 = mul2(x01, C02), t23 = mul2(x23, C02);
        u64 t45 = mul2(x45, C02), t67 = mul2(x67, C02);

        float2 xa, ta;
        xa = unpack2(x01); ta = unpack2(t01);
        float m0 = fmaxf(xa.x, ta.x), m1 = fmaxf(xa.y, ta.y);
        xa = unpack2(x23); ta = unpack2(t23);
        float m2 = fmaxf(xa.x, ta.x), m3 = fmaxf(xa.y, ta.y);
        xa = unpack2(x45); ta = unpack2(t45);
        float m4 = fmaxf(xa.x, ta.x), m5 = fmaxf(xa.y, ta.y);
        xa = unpack2(x67); ta = unpack2(t67);
        float m6 = fmaxf(xa.x, ta.x), m7 = fmaxf(xa.y, ta.y);

        u64 w01 = mul2(pack2(m0, m1), A), w23 = mul2(pack2(m2, m3), A);
        u64 w45 = mul2(pack2(m4, m5), A), w67 = mul2(pack2(m6, m7), A);

        float2 wf;
        wf = unpack2(w01); float e0 = ex2f(wf.x), e1 = ex2f(wf.y);
        wf = unpack2(w23); float e2 = ex2f(wf.x), e3 = ex2f(wf.y);
        wf = unpack2(w45); float e4 = ex2f(wf.x), e5 = ex2f(wf.y);
        wf = unpack2(w67); float e6 = ex2f(wf.x), e7 = ex2f(wf.y);

        u64 e01 = pack2(e0, e1), e23 = pack2(e2, e3);
        u64 e45 = pack2(e4, e5), e67 = pack2(e6, e7);
        u64 sA = add2(e01, e23), sB = add2(e45, e67);
        float2 sc = unpack2(add2(sA, sB));
        float sl = sc.x + sc.y;
        sl += __shfl_xor_sync(0xffffffffu, sl, 1);
        sl += __shfl_xor_sync(0xffffffffu, sl, 2);
        const float inv = rcpf(sl);
        const u64 I = pack2(inv, inv);

        u64 o01 = mul2(e01, I), o23 = mul2(e23, I);
        u64 o45 = mul2(e45, I), o67 = mul2(e67, I);
        rs01 = add2(rs01, o01); rs23 = add2(rs23, o23);
        rs45 = add2(rs45, o45); rs67 = add2(rs67, o67);

        float2 f0 = unpack2(o01), f1 = unpack2(o23);
        float2 f2 = unpack2(o45), f3 = unpack2(o67);
        float* dst = ob + j * (kT * kC);
        *(float4*)dst       = make_float4(f0.x, f0.y, f1.x, f1.y);
        *(float4*)(dst + 4) = make_float4(f2.x, f2.y, f3.x, f3.y);
    }

    // Reduce rsum across the 8 j-subgroups (lane bits 2,3,4)
#pragma unroll
    for (int mask = 4; mask <= 16; mask <<= 1) {
        rs01 = add2(rs01, __shfl_xor_sync(0xffffffffu, rs01, mask));
        rs23 = add2(rs23, __shfl_xor_sync(0xffffffffu, rs23, mask));
        rs45 = add2(rs45, __shfl_xor_sync(0xffffffffu, rs45, mask));
        rs67 = add2(rs67, __shfl_xor_sync(0xffffffffu, rs67, mask));
    }

    if (grp == 0) {   // lanes 0..3 hold full sums for channels 8*cg..8*cg+7
        const int sh = t / kP, ph = t % kP;     // h_flat decomposition of t
        const float* hf = g_h + (b * 6144 + sh * 1536 + i * kP + ph) * 32 + cg * 8;
        const float4 hv0 = *(const float4*)hf;
        const float4 hv1 = *(const float4*)(hf + 4);
        float2 r0 = unpack2(rs01), r1 = unpack2(rs23);
        float2 r2 = unpack2(rs45), r3 = unpack2(rs67);
        float h0 = r0.x * hv0.x, h1 = r0.y * hv0.y;
        float h2 = r1.x * hv0.z, h3 = r1.y * hv0.w;
        float h4 = r2.x * hv1.x, h5 = r2.y * hv1.y;
        float h6 = r3.x * hv1.z, h7 = r3.y * hv1.w;
        float4 o0, o1;
        o0.x = h0 > 0.f ? h0 : expm1f(h0);
        o0.y = h1 > 0.f ? h1 : expm1f(h1);
        o0.z = h2 > 0.f ? h2 : expm1f(h2);
        o0.w = h3 > 0.f ? h3 : expm1f(h3);
        o1.x = h4 > 0.f ? h4 : expm1f(h4);
        o1.y = h5 > 0.f ? h5 : expm1f(h5);
        o1.z = h6 > 0.f ? h6 : expm1f(h6);
        o1.w = h7 > 0.f ? h7 : expm1f(h7);
        float* od = out + kAttElems +
                    ((long long)(b * kN + i) * kT + t) * kC + cg * 8;
        *(float4*)od       = o0;
        *(float4*)(od + 4) = o1;
    }
}

extern "C" void kernel_launch(void* const* d_in, const int* in_sizes, int n_in,
                              void* d_out, int out_size) {
    const float* x   = (const float*)d_in[0];
    const float* adj = (const float*)d_in[1];
    const float* W   = (const float*)d_in[2];
    float* out = (float*)d_out;

    h_kernel<<<(kRows * kC / 4) / 256, 256>>>(x, W);   // 384 blocks

    dim3 grid(kB * kNP * kP, kN / 8);   // (192, 8)
    att_kernel<<<grid, 256>>>(adj, out);
}